// round 3
// baseline (speedup 1.0000x reference)
#include <cuda_runtime.h>
#include <math.h>

#define NUM_Q   8
#define DIM     256
#define N_EMBED 1024
#define NROWS   65536
#define QOUT_ELEMS (NROWS * DIM)

#define TM 64
#define TN 64
#define BK 32
#define NTHREADS 256
#define BSROW 72   // padded Bs row (floats): 16B-aligned, bank-shifted per row

__device__ float g_res[NROWS * DIM];
__device__ float g_embT[NUM_Q * N_EMBED * DIM];
__device__ float g_norms[NUM_Q * N_EMBED];
__device__ float g_losspart[NUM_Q * (NROWS / TM)];
__device__ int   g_counts[NUM_Q * N_EMBED];

typedef unsigned long long ull;
__device__ __forceinline__ ull fma2(ull a, ull b, ull c) {
  ull d; asm("fma.rn.f32x2 %0, %1, %2, %3;" : "=l"(d) : "l"(a), "l"(b), "l"(c));
  return d;
}
__device__ __forceinline__ ull packdup(float x) {
  ull r; asm("mov.b64 %0, {%1, %1};" : "=l"(r) : "f"(x));
  return r;
}
__device__ __forceinline__ float2 unpack2(ull v) {
  float2 f; asm("mov.b64 {%0, %1}, %2;" : "=f"(f.x), "=f"(f.y) : "l"(v));
  return f;
}

// ---------------- prep: transpose codebooks (code-major) + zero counts ----------------
__global__ void prep_kernel(const float* __restrict__ embeds) {
  int idx = blockIdx.x * 256 + threadIdx.x;
  int l = idx >> 18;
  int rem = idx & 262143;
  int d = rem >> 10;
  int k = rem & 1023;
  g_embT[((size_t)l * N_EMBED + k) * DIM + d] = embeds[idx];
  if (idx < NUM_Q * N_EMBED) g_counts[idx] = 0;
}

// ---------------- code norms: sequential d, separate mul+add (XLA reduce) -------------
__global__ void norms_kernel(const float* __restrict__ embeds) {
  int k = blockIdx.x * 256 + threadIdx.x;
  int l = k >> 10;
  int kk = k & 1023;
  float s = 0.f;
  for (int d = 0; d < DIM; ++d) {
    float v = embeds[((size_t)l * DIM + d) * N_EMBED + kk];
    s = __fadd_rn(s, __fmul_rn(v, v));
  }
  g_norms[k] = s;
}

// ---------------- main fused VQ layer ----------------
__global__ void __launch_bounds__(NTHREADS, 2)
vq_layer_kernel(const float* __restrict__ x,
                const float* __restrict__ embeds,
                float* __restrict__ qout,
                int layer) {
  extern __shared__ float sm[];
  float* As   = sm;                          // [TM][DIM]
  float* Bs   = sm + TM * DIM;               // [BK][BSROW]
  int*   sInd = (int*)(Bs + BK * BSROW);     // [TM]
  float* sRN  = (float*)(sInd + TM);         // [TM]
  float* sRed = sRN + TM;                    // [8]

  const int tid = threadIdx.x;
  const int ty = tid >> 4;      // 0..15  rows ty*4..+3
  const int tx = tid & 15;      // 0..15  codes tx*4..+3 within tile
  const int wid = tid >> 5, lane = tid & 31;

  const float* resin = (layer == 0) ? x : g_res;

  // load 64 residual rows into smem (raw fp32 — used for GEMM and epilogue)
  {
    const float4* gsrc = (const float4*)(resin + (size_t)blockIdx.x * TM * DIM);
    float4* dst = (float4*)As;
    #pragma unroll
    for (int i = tid; i < TM * DIM / 4; i += NTHREADS) dst[i] = gsrc[i];
  }
  __syncthreads();

  // ---- ||r||^2 per row, XLA GPU row-reduce pattern: warp-per-row, vec2 strided,
  // ---- two lane partials combined, then shfl.down tree 16/8/4/2/1 ----
  #pragma unroll 1
  for (int rr = 0; rr < 8; ++rr) {
    int row = wid * 8 + rr;
    const float* rp = As + row * DIM;
    float p0 = 0.f, p1 = 0.f;
    #pragma unroll
    for (int i = 0; i < 4; ++i) {
      float2 v = *(const float2*)&rp[i * 64 + 2 * lane];
      p0 = __fadd_rn(p0, __fmul_rn(v.x, v.x));
      p1 = __fadd_rn(p1, __fmul_rn(v.y, v.y));
    }
    float a = __fadd_rn(p0, p1);
    #pragma unroll
    for (int off = 16; off > 0; off >>= 1)
      a = __fadd_rn(a, __shfl_down_sync(0xffffffff, a, off));
    if (lane == 0) sRN[row] = a;
  }
  __syncthreads();

  float bestv[4];
  int   besti[4];
  #pragma unroll
  for (int i = 0; i < 4; ++i) { bestv[i] = 3.4028235e38f; besti[i] = 0; }

  const int dr  = tid >> 3;        // 0..31 k-row within chunk
  const int dcb = (tid & 7) * 8;   // code base for Bs loads

  for (int ct = 0; ct < N_EMBED / TN; ++ct) {
    // 8 independent sequential-k accumulator chains: 4 rows x 2 code-pairs
    ull acc[4][2];
    #pragma unroll
    for (int i = 0; i < 4; ++i) { acc[i][0] = 0ull; acc[i][1] = 0ull; }

    for (int kc = 0; kc < DIM / BK; ++kc) {
      __syncthreads();
      {
        const float* g = embeds + ((size_t)(layer * DIM + kc * BK + dr)) * N_EMBED
                         + ct * TN + dcb;
        float4 v0 = *(const float4*)g;
        float4 v1 = *(const float4*)(g + 4);
        *(float4*)&Bs[dr * BSROW + dcb]     = v0;
        *(float4*)&Bs[dr * BSROW + dcb + 4] = v1;
      }
      __syncthreads();

      const float* ap = As + (ty * 4) * DIM + kc * BK;
      #pragma unroll
      for (int dd = 0; dd < BK; dd += 2) {
        ulonglong2 b0 = *(const ulonglong2*)&Bs[dd * BSROW + tx * 4];
        ulonglong2 b1 = *(const ulonglong2*)&Bs[(dd + 1) * BSROW + tx * 4];
        #pragma unroll
        for (int i = 0; i < 4; ++i) {
          float a0 = ap[i * DIM + dd];
          float a1 = ap[i * DIM + dd + 1];
          ull alo = packdup(a0), ahi = packdup(a1);
          // strictly ascending k per accumulator lane (sequential FMA chain)
          acc[i][0] = fma2(alo, b0.x, acc[i][0]);
          acc[i][1] = fma2(alo, b0.y, acc[i][1]);
          acc[i][0] = fma2(ahi, b1.x, acc[i][0]);
          acc[i][1] = fma2(ahi, b1.y, acc[i][1]);
        }
      }
    }

    // dist = (rn - 2*ab) + en, exact reference association, no contraction
    #pragma unroll
    for (int i = 0; i < 4; ++i) {
      float rn = sRN[ty * 4 + i];
      #pragma unroll
      for (int jp = 0; jp < 2; ++jp) {
        float2 s = unpack2(acc[i][jp]);
        int code0 = ct * TN + tx * 4 + jp * 2;
        float en0 = __ldg(&g_norms[layer * N_EMBED + code0]);
        float en1 = __ldg(&g_norms[layer * N_EMBED + code0 + 1]);
        float d0 = __fadd_rn(__fadd_rn(rn, __fmul_rn(-2.0f, s.x)), en0);
        float d1 = __fadd_rn(__fadd_rn(rn, __fmul_rn(-2.0f, s.y)), en1);
        if (d0 < bestv[i]) { bestv[i] = d0; besti[i] = code0; }
        if (d1 < bestv[i]) { bestv[i] = d1; besti[i] = code0 + 1; }
      }
    }
  }

  // argmin across the 16 tx lanes (xor butterfly within half-warp), first-index ties
  #pragma unroll
  for (int off = 1; off < 16; off <<= 1) {
    #pragma unroll
    for (int i = 0; i < 4; ++i) {
      float ov = __shfl_xor_sync(0xffffffff, bestv[i], off);
      int   oi = __shfl_xor_sync(0xffffffff, besti[i], off);
      if (ov < bestv[i] || (ov == bestv[i] && oi < besti[i])) {
        bestv[i] = ov; besti[i] = oi;
      }
    }
  }
  if (tx == 0) {
    #pragma unroll
    for (int i = 0; i < 4; ++i) sInd[ty * 4 + i] = besti[i];
  }
  __syncthreads();

  // ------------- epilogue: exact straight-through chain -------------
  float lsum = 0.f;
  const size_t rowbase = (size_t)blockIdx.x * TM;

  #pragma unroll 1
  for (int rr = 0; rr < 8; ++rr) {
    int r = wid * 8 + rr;
    int c = sInd[r];
    const float* q   = g_embT + ((size_t)layer * N_EMBED + c) * DIM;
    float* outp      = qout  + (rowbase + r) * DIM;
    float* resp      = g_res + (rowbase + r) * DIM;
    const float* rsm = As + r * DIM;
    #pragma unroll
    for (int h = 0; h < 2; ++h) {
      int d = lane * 4 + h * 128;
      float4 qv = *(const float4*)(q + d);
      float4 rv = *(const float4*)(rsm + d);
      float4 dq, qst, nr;
      dq.x = __fadd_rn(qv.x, -rv.x); dq.y = __fadd_rn(qv.y, -rv.y);
      dq.z = __fadd_rn(qv.z, -rv.z); dq.w = __fadd_rn(qv.w, -rv.w);
      qst.x = __fadd_rn(rv.x, dq.x); qst.y = __fadd_rn(rv.y, dq.y);
      qst.z = __fadd_rn(rv.z, dq.z); qst.w = __fadd_rn(rv.w, dq.w);
      nr.x = __fadd_rn(rv.x, -qst.x); nr.y = __fadd_rn(rv.y, -qst.y);
      nr.z = __fadd_rn(rv.z, -qst.z); nr.w = __fadd_rn(rv.w, -qst.w);
      *(float4*)(resp + d) = nr;
      float4 ov;
      if (layer == 0) {
        ov = qst;  // 0 + qst
      } else {
        ov = *(const float4*)(outp + d);
        ov.x = __fadd_rn(ov.x, qst.x); ov.y = __fadd_rn(ov.y, qst.y);
        ov.z = __fadd_rn(ov.z, qst.z); ov.w = __fadd_rn(ov.w, qst.w);
      }
      *(float4*)(outp + d) = ov;
      // loss uses (quantize - residual)^2 = dq^2
      lsum += __fmul_rn(dq.x, dq.x) + __fmul_rn(dq.y, dq.y)
            + __fmul_rn(dq.z, dq.z) + __fmul_rn(dq.w, dq.w);
    }
    if (lane == 0) atomicAdd(&g_counts[layer * N_EMBED + c], 1);
  }

  #pragma unroll
  for (int off = 16; off > 0; off >>= 1)
    lsum += __shfl_xor_sync(0xffffffff, lsum, off);
  if (lane == 0) sRed[wid] = lsum;
  __syncthreads();
  if (tid == 0) {
    float s = 0.f;
    #pragma unroll
    for (int w = 0; w < 8; ++w) s += sRed[w];
    g_losspart[layer * (NROWS / TM) + blockIdx.x] = s;
  }
}

// ---------------- finalize: loss mean + perplexity ----------------
__global__ void finalize_kernel(float* __restrict__ out) {
  const int l = blockIdx.x;
  const int tid = threadIdx.x;
  __shared__ double sd[256];
  __shared__ float  sf[256];
  double ls = 0.0;
  float  es = 0.f;
  for (int i = tid; i < NROWS / TM; i += 256)
    ls += (double)g_losspart[l * (NROWS / TM) + i];
  for (int i = tid; i < N_EMBED; i += 256) {
    float p = (float)g_counts[l * N_EMBED + i] * (1.0f / (float)NROWS);
    es += p * logf(__fadd_rn(p, 1e-10f));
  }
  sd[tid] = ls; sf[tid] = es;
  __syncthreads();
  for (int s = 128; s > 0; s >>= 1) {
    if (tid < s) { sd[tid] += sd[tid + s]; sf[tid] += sf[tid + s]; }
    __syncthreads();
  }
  if (tid == 0) {
    out[QOUT_ELEMS + l]         = (float)(sd[0] / (double)QOUT_ELEMS);
    out[QOUT_ELEMS + NUM_Q + l] = expf(-sf[0]);
  }
}

extern "C" void kernel_launch(void* const* d_in, const int* in_sizes, int n_in,
                              void* d_out, int out_size) {
  const float* x      = (const float*)d_in[0];
  const float* embeds = (const float*)d_in[1];
  float* out          = (float*)d_out;

  const int smem_bytes = (TM * DIM + BK * BSROW) * 4 + TM * 4 + TM * 4 + 8 * 4;
  cudaFuncSetAttribute(vq_layer_kernel,
                       cudaFuncAttributeMaxDynamicSharedMemorySize, smem_bytes);

  prep_kernel<<<(NUM_Q * N_EMBED * DIM) / 256, 256>>>(embeds);
  norms_kernel<<<(NUM_Q * N_EMBED) / 256, 256>>>(embeds);

  for (int l = 0; l < NUM_Q; ++l) {
    vq_layer_kernel<<<NROWS / TM, NTHREADS, smem_bytes>>>(x, embeds, out, l);
  }
  finalize_kernel<<<NUM_Q, 256>>>(out);
}